// round 4
// baseline (speedup 1.0000x reference)
#include <cuda_runtime.h>
#include <math.h>

typedef unsigned long long ull;

#define THREADS 1024
#define NSTATE  16384

// aux float offsets (aux = sm + 2*NSTATE floats)
#define OF_GATE 0      // 42 gates * 8 floats: [ca,ca,-sa,-sa,sa,sa,pad,pad]
#define OF_PHI  336    // 42 (half-angles phi = 0.5*theta for RZ)
#define OF_ENC_C 384   // 14
#define OF_ENC_S 400   // 14
#define OF_RTAB 416    // 16
#define OF_PRB  432    // 2 layers * 16 entries * 4 floats (16B aligned)
#define OF_TLO  560    // 128
#define OF_THI  688    // 128
#define OF_WARP 816    // 32
#define AUXF    848
#define SMEM_BYTES ((2 * NSTATE + AUXF) * sizeof(float))

__device__ __forceinline__ ull pk(float lo, float hi) {
    ull r; asm("mov.b64 %0, {%1,%2};" : "=l"(r) : "f"(lo), "f"(hi)); return r;
}
__device__ __forceinline__ void upk(ull v, float& lo, float& hi) {
    asm("mov.b64 {%0,%1}, %2;" : "=f"(lo), "=f"(hi) : "l"(v));
}
__device__ __forceinline__ ull swap2(ull v) {
    float lo, hi;
    asm("mov.b64 {%0,%1}, %2;" : "=f"(lo), "=f"(hi) : "l"(v));
    ull r; asm("mov.b64 %0, {%1,%2};" : "=l"(r) : "f"(hi), "f"(lo)); return r;
}
__device__ __forceinline__ ull mul2(ull a, ull b) {
    ull d; asm("mul.rn.f32x2 %0, %1, %2;" : "=l"(d) : "l"(a), "l"(b)); return d;
}
__device__ __forceinline__ ull fma2(ull a, ull b, ull c) {
    ull d; asm("fma.rn.f32x2 %0, %1, %2, %3;" : "=l"(d) : "l"(a), "l"(b), "l"(c)); return d;
}
// multiply packed complex A by phase (cr2=(c,c), cn2=(-s,s)) : A * e^{i psi}
__device__ __forceinline__ ull phmul(ull A, ull cr2, ull cn2) {
    return fma2(cn2, swap2(A), mul2(cr2, A));
}
// RY on a register pair
__device__ __forceinline__ void pair_ry(ull& A0, ull& A1, ull ca2, ull nsa2, ull sa2) {
    ull T0 = fma2(nsa2, A1, mul2(ca2, A0));
    ull T1 = fma2(sa2,  A0, mul2(ca2, A1));
    A0 = T0; A1 = T1;
}

__global__ __launch_bounds__(THREADS, 1)
void qsim_kernel(const float* __restrict__ state,   // [256,14]
                 const float* __restrict__ vp,      // [3,14,3]
                 const float* __restrict__ hw,      // [14]
                 const float* __restrict__ hb,      // [1]
                 float* __restrict__ out)           // [256]
{
    extern __shared__ float sm[];
    ull*   psi = (ull*)sm;                 // 16384 packed (re,im)
    float* aux = sm + 2 * NSTATE;

    const int tid  = threadIdx.x;
    const int lane = tid & 31;
    const int wa   = tid >> 5;

    // ---- setup stage 1 ----
    if (tid < 42) {
        float a = 0.5f * vp[tid * 3 + 0];
        float ca, sa;
        sincosf(a, &sa, &ca);
        float* g = aux + OF_GATE + tid * 8;
        g[0] = ca;  g[1] = ca;
        g[2] = -sa; g[3] = -sa;
        g[4] = sa;  g[5] = sa;
        aux[OF_PHI + tid] = 0.5f * vp[tid * 3 + 1];
    } else if (tid >= 64 && tid < 78) {
        int w = tid - 64;
        float h = 0.5f * state[blockIdx.x * 14 + w];
        float c, s;
        sincosf(h, &s, &c);
        aux[OF_ENC_C + w] = c;
        aux[OF_ENC_S + w] = s;
    } else if (tid >= 128 && tid < 256) {
        int x = tid - 128;
        float a2 = 0.f;
        #pragma unroll
        for (int p = 0; p < 7; p++)
            a2 += (((x >> p) & 1) ? -1.f : 1.f) * hw[13 - p];
        aux[OF_TLO + x] = a2;
    } else if (tid >= 256 && tid < 384) {
        int x = tid - 256;
        float a2 = 0.f;
        #pragma unroll
        for (int p = 0; p < 7; p++)
            a2 += (((x >> p) & 1) ? -1.f : 1.f) * hw[6 - p];
        aux[OF_THI + x] = a2;
    }
    __syncthreads();

    // ---- setup stage 2 ----
    if (tid < 16) {
        // rtab: product of RX factors for idx bits 10..13 (wires 3..0)
        float m = 1.f;
        #pragma unroll
        for (int j = 0; j < 4; j++)
            m *= ((tid >> j) & 1) ? aux[OF_ENC_S + 3 - j] : aux[OF_ENC_C + 3 - j];
        aux[OF_RTAB + tid] = m;
    } else if (tid >= 32 && tid < 64) {
        // PRB: RZ phase table over pass-B local bits (wires 4..7), layers 0,1
        int idx = tid - 32;
        int l = idx >> 4, r = idx & 15;
        float ang = 0.f;
        #pragma unroll
        for (int j = 0; j < 4; j++)
            ang += (((r >> j) & 1) ? 1.f : -1.f) * aux[OF_PHI + l * 14 + 7 - j];
        float c, s;
        sincosf(ang, &s, &c);
        float* p = aux + OF_PRB + (l * 16 + r) * 4;
        p[0] = c; p[1] = c; p[2] = -s; p[3] = s;
    }
    // per-thread RX base product over tid bits 0..9 (wires 13..4)
    float P = 1.f;
    #pragma unroll
    for (int j = 0; j < 10; j++)
        P *= ((tid >> j) & 1) ? aux[OF_ENC_S + 13 - j] : aux[OF_ENC_C + 13 - j];
    int pt = __popc(tid);
    __syncthreads();

    // ---- init directly in pass-A register layout: e = tid | (r<<10) ----
    ull A[16];
    #pragma unroll
    for (int r = 0; r < 16; r++) {
        float mag = P * aux[OF_RTAB + r];
        int k = (pt + __popc(r)) & 3;
        float sg = (k == 1 || k == 2) ? -mag : mag;
        float re_ = (k & 1) ? 0.f : sg;
        float im_ = (k & 1) ? sg : 0.f;
        A[r] = pk(re_, im_);
    }

    float acc = 0.f;
    const int baseB = (lane & 15) | ((wa & 1) << 4) | (((lane >> 4) & 1) << 5)
                    | ((wa >> 1) << 10);

    #pragma unroll 1
    for (int l = 0; l < 3; l++) {
        // ======== Pass A: e = tid | (r<<10); wires 9-13 shfl, 0-3 local ========
        if (l) {
            // gray-folded CNOT perm of previous layer
            #pragma unroll
            for (int r = 0; r < 16; r++) {
                int e = tid | (r << 10);
                A[r] = psi[e ^ (e >> 1)];
            }
            __syncthreads();   // drain gathers before scatter below
        }
        // shfl RY: wires 9..13 (idx bits 4..0 = lane bits)
        #pragma unroll
        for (int w = 9; w < 14; w++) {
            const ull* g = (const ull*)(aux + OF_GATE + (l * 14 + w) * 8);
            int bit = 13 - w;
            ull ca2 = g[0];
            ull sp2 = ((lane >> bit) & 1) ? g[2] : g[1];  // +sa : -sa
            unsigned mask = 1u << bit;
            #pragma unroll
            for (int r = 0; r < 16; r++) {
                ull Pp = __shfl_xor_sync(0xffffffffu, A[r], mask);
                A[r] = fma2(sp2, Pp, mul2(ca2, A[r]));
            }
        }
        // pair RY: wires 0..3 (local r-bit 3-w)
        #pragma unroll
        for (int w = 0; w < 4; w++) {
            const ull* g = (const ull*)(aux + OF_GATE + (l * 14 + w) * 8);
            ull ca2 = g[0], nsa2 = g[1], sa2 = g[2];
            int bj = 1 << (3 - w);
            #pragma unroll
            for (int r = 0; r < 16; r++)
                if (!(r & bj))
                    pair_ry(A[r], A[r | bj], ca2, nsa2, sa2);
        }
        #pragma unroll
        for (int r = 0; r < 16; r++)
            psi[tid | (r << 10)] = A[r];
        __syncthreads();

        // ======== Pass B: e = baseB | (r<<6); wires 4-7 local, wire 8 shfl ========
        #pragma unroll
        for (int r = 0; r < 16; r++)
            A[r] = psi[baseB | (r << 6)];
        #pragma unroll
        for (int w = 4; w < 8; w++) {
            const ull* g = (const ull*)(aux + OF_GATE + (l * 14 + w) * 8);
            ull ca2 = g[0], nsa2 = g[1], sa2 = g[2];
            int bj = 1 << (7 - w);
            #pragma unroll
            for (int r = 0; r < 16; r++)
                if (!(r & bj))
                    pair_ry(A[r], A[r | bj], ca2, nsa2, sa2);
        }
        {   // wire 8 via shfl on lane bit 4 (idx bit 5)
            const ull* g = (const ull*)(aux + OF_GATE + (l * 14 + 8) * 8);
            ull ca2 = g[0];
            ull sp2 = ((lane >> 4) & 1) ? g[2] : g[1];
            #pragma unroll
            for (int r = 0; r < 16; r++) {
                ull Pp = __shfl_xor_sync(0xffffffffu, A[r], 16);
                A[r] = fma2(sp2, Pp, mul2(ca2, A[r]));
            }
        }

        if (l < 2) {
            // ---- deferred RZ: all 14 wires' phases, applied once ----
            // thread-constant bits: 13..10 = wa>>1 (wires 0-3), 5 = lane4 (wire 8),
            // 4 = wa&1 (wire 9), 3..0 = lane (wires 10-13)
            const float* ph = aux + OF_PHI + l * 14;
            int hb = wa >> 1;
            float ang = 0.f;
            ang += (((hb >> 3) & 1) ? 1.f : -1.f) * ph[0];
            ang += (((hb >> 2) & 1) ? 1.f : -1.f) * ph[1];
            ang += (((hb >> 1) & 1) ? 1.f : -1.f) * ph[2];
            ang += (( hb       & 1) ? 1.f : -1.f) * ph[3];
            ang += (((lane >> 4) & 1) ? 1.f : -1.f) * ph[8];
            ang += (( wa        & 1) ? 1.f : -1.f) * ph[9];
            ang += (((lane >> 3) & 1) ? 1.f : -1.f) * ph[10];
            ang += (((lane >> 2) & 1) ? 1.f : -1.f) * ph[11];
            ang += (((lane >> 1) & 1) ? 1.f : -1.f) * ph[12];
            ang += (( lane      & 1) ? 1.f : -1.f) * ph[13];
            float cc, ss;
            sincosf(ang, &ss, &cc);
            ull pc2 = pk(cc, cc), pn2 = pk(-ss, ss);
            const ull* prb = (const ull*)(aux + OF_PRB + l * 64);
            #pragma unroll
            for (int r = 0; r < 16; r++) {
                A[r] = phmul(A[r], pc2, pn2);
                A[r] = phmul(A[r], prb[2 * r], prb[2 * r + 1]);
            }
            #pragma unroll
            for (int r = 0; r < 16; r++)
                psi[baseB | (r << 6)] = A[r];
            __syncthreads();
        } else {
            // last layer: RZ phases are unobservable; fold CNOT perm + <Z> + head
            #pragma unroll
            for (int r = 0; r < 16; r++) {
                int e = baseB | (r << 6);
                int gg = e;
                gg ^= gg >> 1; gg ^= gg >> 2; gg ^= gg >> 4; gg ^= gg >> 8;
                float wt = aux[OF_TLO + (gg & 127)] + aux[OF_THI + ((gg >> 7) & 127)];
                float x, y; upk(A[r], x, y);
                acc = fmaf(fmaf(x, x, y * y), wt, acc);
            }
        }
    }

    // ---- block reduction ----
    #pragma unroll
    for (int o = 16; o; o >>= 1)
        acc += __shfl_xor_sync(0xffffffffu, acc, o);
    if (lane == 0)
        aux[OF_WARP + wa] = acc;
    __syncthreads();
    if (tid < 32) {
        float v = aux[OF_WARP + tid];
        #pragma unroll
        for (int o = 16; o; o >>= 1)
            v += __shfl_xor_sync(0xffffffffu, v, o);
        if (tid == 0)
            out[blockIdx.x] = v + hb[0];
    }
}

extern "C" void kernel_launch(void* const* d_in, const int* in_sizes, int n_in,
                              void* d_out, int out_size)
{
    const float* state = (const float*)d_in[0];
    const float* vp    = (const float*)d_in[1];
    const float* hw    = (const float*)d_in[2];
    const float* hb    = (const float*)d_in[3];
    float* out = (float*)d_out;

    cudaFuncSetAttribute(qsim_kernel,
                         cudaFuncAttributeMaxDynamicSharedMemorySize,
                         (int)SMEM_BYTES);
    qsim_kernel<<<256, THREADS, SMEM_BYTES>>>(state, vp, hw, hb, out);
}

// round 6
// speedup vs baseline: 1.3461x; 1.3461x over previous
#include <cuda_runtime.h>
#include <math.h>

typedef unsigned long long ull;

#define THREADS 1024
#define NSTATE  16384

// aux float offsets (aux = sm + 2*NSTATE floats)
#define OF_GATE 0      // 42 gates * 12 floats (packed coef pairs)
#define OF_ENC_C 512   // 14
#define OF_ENC_S 528   // 14
#define OF_RTAB 544    // 16
#define OF_TLO  576    // 128
#define OF_THI  704    // 128
#define OF_WARP 832    // 32
#define AUXF    864
#define SMEM_BYTES ((2 * NSTATE + AUXF) * sizeof(float))

__device__ __forceinline__ ull pk(float lo, float hi) {
    ull r; asm("mov.b64 %0, {%1,%2};" : "=l"(r) : "f"(lo), "f"(hi)); return r;
}
__device__ __forceinline__ void upk(ull v, float& lo, float& hi) {
    asm("mov.b64 {%0,%1}, %2;" : "=f"(lo), "=f"(hi) : "l"(v));
}
__device__ __forceinline__ ull swap2(ull v) {
    float lo, hi;
    asm("mov.b64 {%0,%1}, %2;" : "=f"(lo), "=f"(hi) : "l"(v));
    ull r; asm("mov.b64 %0, {%1,%2};" : "=l"(r) : "f"(hi), "f"(lo)); return r;
}
__device__ __forceinline__ ull mul2(ull a, ull b) {
    ull d; asm("mul.rn.f32x2 %0, %1, %2;" : "=l"(d) : "l"(a), "l"(b)); return d;
}
__device__ __forceinline__ ull fma2(ull a, ull b, ull c) {
    ull d; asm("fma.rn.f32x2 %0, %1, %2, %3;" : "=l"(d) : "l"(a), "l"(b), "l"(c)); return d;
}

// Fused RY+RZ on a pair of packed (re,im) amplitudes.
__device__ __forceinline__ void pair_gate(ull& A0, ull& A1,
                                          ull ca2, ull nsa2, ull sa2,
                                          ull cf2, ull ph0, ull ph1) {
    ull T0 = fma2(nsa2, A1, mul2(ca2, A0));
    ull T1 = fma2(sa2,  A0, mul2(ca2, A1));
    A0 = fma2(ph0, swap2(T0), mul2(cf2, T0));
    A1 = fma2(ph1, swap2(T1), mul2(cf2, T1));
}
// RY-only pair gate (last layer: RZ unobservable)
__device__ __forceinline__ void pair_ry(ull& A0, ull& A1,
                                        ull ca2, ull nsa2, ull sa2) {
    ull T0 = fma2(nsa2, A1, mul2(ca2, A0));
    ull T1 = fma2(sa2,  A0, mul2(ca2, A1));
    A0 = T0; A1 = T1;
}
// Fused RY+RZ when partner lives in another lane.
__device__ __forceinline__ void shfl_gate(ull& A, unsigned mask,
                                          ull ca2, ull sp, ull cf2, ull ph) {
    ull P = __shfl_xor_sync(0xffffffffu, A, mask);
    ull T = fma2(sp, P, mul2(ca2, A));
    A = fma2(ph, swap2(T), mul2(cf2, T));
}
// RY-only shfl gate
__device__ __forceinline__ void shfl_ry(ull& A, unsigned mask, ull ca2, ull sp) {
    ull P = __shfl_xor_sync(0xffffffffu, A, mask);
    A = fma2(sp, P, mul2(ca2, A));
}

__global__ __launch_bounds__(THREADS, 1)
void qsim_kernel(const float* __restrict__ state,   // [256,14]
                 const float* __restrict__ vp,      // [3,14,3]
                 const float* __restrict__ hw,      // [14]
                 const float* __restrict__ hb,      // [1]
                 float* __restrict__ out)           // [256]
{
    extern __shared__ float sm[];
    ull*   psi = (ull*)sm;                 // 16384 packed (re,im)
    float* aux = sm + 2 * NSTATE;

    const int tid  = threadIdx.x;
    const int lane = tid & 31;
    const int wa   = tid >> 5;

    // ---- setup: gate coef packs, encoding cos/sin, weight tables ----
    if (tid < 42) {
        float a  = 0.5f * vp[tid * 3 + 0];
        float th = 0.5f * vp[tid * 3 + 1];
        float ca, sa, cf, sf;
        sincosf(a,  &sa, &ca);
        sincosf(th, &sf, &cf);
        float* g = aux + OF_GATE + tid * 12;
        g[0] = ca;  g[1] = ca;          // ca2
        g[2] = -sa; g[3] = -sa;         // nsa2
        g[4] = sa;  g[5] = sa;          // sa2
        g[6] = cf;  g[7] = cf;          // cf2
        g[8] = sf;  g[9] = -sf;         // ph0 = (sf,-sf)
        g[10] = -sf; g[11] = sf;        // ph1 = (-sf,sf)
    } else if (tid >= 64 && tid < 78) {
        int w = tid - 64;
        float h = 0.5f * state[blockIdx.x * 14 + w];
        float c, s;
        sincosf(h, &s, &c);
        aux[OF_ENC_C + w] = c;
        aux[OF_ENC_S + w] = s;
    } else if (tid >= 128 && tid < 256) {
        int x = tid - 128;
        float a2 = 0.f;
        #pragma unroll
        for (int p = 0; p < 7; p++)
            a2 += (((x >> p) & 1) ? -1.f : 1.f) * hw[13 - p];
        aux[OF_TLO + x] = a2;
    } else if (tid >= 256 && tid < 384) {
        int x = tid - 256;
        float a2 = 0.f;
        #pragma unroll
        for (int p = 0; p < 7; p++)
            a2 += (((x >> p) & 1) ? -1.f : 1.f) * hw[6 - p];
        aux[OF_THI + x] = a2;
    }
    __syncthreads();

    // rtab: product of RX factors for idx bits 10..13 (wires 3..0)
    if (tid < 16) {
        float m = 1.f;
        #pragma unroll
        for (int j = 0; j < 4; j++)
            m *= ((tid >> j) & 1) ? aux[OF_ENC_S + 3 - j] : aux[OF_ENC_C + 3 - j];
        aux[OF_RTAB + tid] = m;
    }
    // per-thread RX base product over tid bits 0..9 (wires 13..4)
    float P = 1.f;
    #pragma unroll
    for (int j = 0; j < 10; j++)
        P *= ((tid >> j) & 1) ? aux[OF_ENC_S + 13 - j] : aux[OF_ENC_C + 13 - j];
    int pt = __popc(tid);
    __syncthreads();

    // ---- init directly in pass-A register layout: e = tid | (r<<10) ----
    ull A[16];
    #pragma unroll
    for (int r = 0; r < 16; r++) {
        float mag = P * aux[OF_RTAB + r];
        int k = (pt + __popc(r)) & 3;
        float sg = (k == 1 || k == 2) ? -mag : mag;
        float re_ = (k & 1) ? 0.f : sg;
        float im_ = (k & 1) ? sg : 0.f;
        A[r] = pk(re_, im_);
    }

    float acc = 0.f;
    // pass-B layout: idx bit 4 <- wa&1 (wire 9, already done in pass A),
    //                idx bit 5 <- lane bit 4 (wire 8, shfl mask 16)
    const int baseB = (lane & 15) | ((wa & 1) << 4) | (((lane >> 4) & 1) << 5)
                    | ((wa >> 1) << 10);

    #pragma unroll 1
    for (int l = 0; l < 3; l++) {
        // ======== Pass A: e = tid | (r<<10); wires 9-13 shfl, 0-3 local ========
        if (l) {
            // gray-folded CNOT perm of previous layer
            #pragma unroll
            for (int r = 0; r < 16; r++) {
                int e = tid | (r << 10);
                A[r] = psi[e ^ (e >> 1)];
            }
            __syncthreads();   // drain gathers before scatter below
        }
        // shfl gates: wires 9..13 (idx bits 4..0 = lane bits)
        #pragma unroll
        for (int w = 9; w < 14; w++) {
            const ull* g = (const ull*)(aux + OF_GATE + (l * 14 + w) * 12);
            int bit = 13 - w;
            int b = (lane >> bit) & 1;
            ull ca2 = g[0];
            ull sp  = b ? g[2] : g[1];
            unsigned mask = 1u << bit;
            if (l < 2) {
                ull cf2 = g[3];
                ull ph  = b ? g[5] : g[4];
                #pragma unroll
                for (int r = 0; r < 16; r++)
                    shfl_gate(A[r], mask, ca2, sp, cf2, ph);
            } else {
                #pragma unroll
                for (int r = 0; r < 16; r++)
                    shfl_ry(A[r], mask, ca2, sp);
            }
        }
        // pair gates: wires 0..3 (local r-bit 3-w)
        #pragma unroll
        for (int w = 0; w < 4; w++) {
            const ull* g = (const ull*)(aux + OF_GATE + (l * 14 + w) * 12);
            int bj = 1 << (3 - w);
            if (l < 2) {
                #pragma unroll
                for (int r = 0; r < 16; r++)
                    if (!(r & bj))
                        pair_gate(A[r], A[r | bj], g[0], g[1], g[2], g[3], g[4], g[5]);
            } else {
                #pragma unroll
                for (int r = 0; r < 16; r++)
                    if (!(r & bj))
                        pair_ry(A[r], A[r | bj], g[0], g[1], g[2]);
            }
        }
        #pragma unroll
        for (int r = 0; r < 16; r++)
            psi[tid | (r << 10)] = A[r];
        __syncthreads();

        // ======== Pass B: e = baseB | (r<<6); wires 4-7 local, wire 8 shfl ========
        #pragma unroll
        for (int r = 0; r < 16; r++)
            A[r] = psi[baseB | (r << 6)];
        #pragma unroll
        for (int w = 4; w < 8; w++) {
            const ull* g = (const ull*)(aux + OF_GATE + (l * 14 + w) * 12);
            int bj = 1 << (7 - w);
            if (l < 2) {
                #pragma unroll
                for (int r = 0; r < 16; r++)
                    if (!(r & bj))
                        pair_gate(A[r], A[r | bj], g[0], g[1], g[2], g[3], g[4], g[5]);
            } else {
                #pragma unroll
                for (int r = 0; r < 16; r++)
                    if (!(r & bj))
                        pair_ry(A[r], A[r | bj], g[0], g[1], g[2]);
            }
        }
        {   // wire 8 via shfl on lane bit 4 (idx bit 5)
            const ull* g = (const ull*)(aux + OF_GATE + (l * 14 + 8) * 12);
            int b = (lane >> 4) & 1;
            ull ca2 = g[0];
            ull sp  = b ? g[2] : g[1];
            if (l < 2) {
                ull cf2 = g[3];
                ull ph  = b ? g[5] : g[4];
                #pragma unroll
                for (int r = 0; r < 16; r++)
                    shfl_gate(A[r], 16u, ca2, sp, cf2, ph);
            } else {
                #pragma unroll
                for (int r = 0; r < 16; r++)
                    shfl_ry(A[r], 16u, ca2, sp);
            }
        }

        if (l < 2) {
            #pragma unroll
            for (int r = 0; r < 16; r++)
                psi[baseB | (r << 6)] = A[r];
            __syncthreads();
        } else {
            // fold final CNOT perm + <Z> + linear head: stored e -> grayDecode(e)
            #pragma unroll
            for (int r = 0; r < 16; r++) {
                int e = baseB | (r << 6);
                int gg = e;
                gg ^= gg >> 1; gg ^= gg >> 2; gg ^= gg >> 4; gg ^= gg >> 8;
                float wt = aux[OF_TLO + (gg & 127)] + aux[OF_THI + ((gg >> 7) & 127)];
                float x, y; upk(A[r], x, y);
                acc = fmaf(fmaf(x, x, y * y), wt, acc);
            }
        }
    }

    // ---- block reduction ----
    #pragma unroll
    for (int o = 16; o; o >>= 1)
        acc += __shfl_xor_sync(0xffffffffu, acc, o);
    if (lane == 0)
        aux[OF_WARP + wa] = acc;
    __syncthreads();
    if (tid < 32) {
        float v = aux[OF_WARP + tid];
        #pragma unroll
        for (int o = 16; o; o >>= 1)
            v += __shfl_xor_sync(0xffffffffu, v, o);
        if (tid == 0)
            out[blockIdx.x] = v + hb[0];
    }
}

extern "C" void kernel_launch(void* const* d_in, const int* in_sizes, int n_in,
                              void* d_out, int out_size)
{
    const float* state = (const float*)d_in[0];
    const float* vp    = (const float*)d_in[1];
    const float* hw    = (const float*)d_in[2];
    const float* hb    = (const float*)d_in[3];
    float* out = (float*)d_out;

    cudaFuncSetAttribute(qsim_kernel,
                         cudaFuncAttributeMaxDynamicSharedMemorySize,
                         (int)SMEM_BYTES);
    qsim_kernel<<<256, THREADS, SMEM_BYTES>>>(state, vp, hw, hb, out);
}

// round 7
// speedup vs baseline: 1.5305x; 1.1370x over previous
#include <cuda_runtime.h>
#include <math.h>

typedef unsigned long long ull;

#define THREADS 1024
#define NSTATE  16384

// aux float offsets (aux = sm + 2*NSTATE floats)
#define OF_GATE 0      // 42 gates * 8 floats: [ca,ca,-sa,-sa,sa,sa,cf,sf]
#define OF_ENC_C 336   // 14
#define OF_ENC_S 352   // 14
#define OF_RTAB 368    // 16
#define OF_PA   384    // 2 layers * 16 * 4 floats  (phase table, wires 0-3)
#define OF_PB   512    // 2 layers * 16 * 4 floats  (phase table, wires 4-7)
#define OF_TLO  640    // 128
#define OF_THI  768    // 128
#define OF_WARP 896    // 32
#define AUXF    928
#define SMEM_BYTES ((2 * NSTATE + AUXF) * sizeof(float))

__device__ __forceinline__ ull pk(float lo, float hi) {
    ull r; asm("mov.b64 %0, {%1,%2};" : "=l"(r) : "f"(lo), "f"(hi)); return r;
}
__device__ __forceinline__ void upk(ull v, float& lo, float& hi) {
    asm("mov.b64 {%0,%1}, %2;" : "=f"(lo), "=f"(hi) : "l"(v));
}
__device__ __forceinline__ ull swap2(ull v) {
    float lo, hi;
    asm("mov.b64 {%0,%1}, %2;" : "=f"(lo), "=f"(hi) : "l"(v));
    ull r; asm("mov.b64 %0, {%1,%2};" : "=l"(r) : "f"(hi), "f"(lo)); return r;
}
__device__ __forceinline__ ull mul2(ull a, ull b) {
    ull d; asm("mul.rn.f32x2 %0, %1, %2;" : "=l"(d) : "l"(a), "l"(b)); return d;
}
__device__ __forceinline__ ull fma2(ull a, ull b, ull c) {
    ull d; asm("fma.rn.f32x2 %0, %1, %2, %3;" : "=l"(d) : "l"(a), "l"(b), "l"(c)); return d;
}
// A * e^{i a}: cr2 = (cos a, cos a), cn2 = (-sin a, sin a)
__device__ __forceinline__ ull phmul(ull A, ull cr2, ull cn2) {
    return fma2(cn2, swap2(A), mul2(cr2, A));
}
// RY on a register pair (real matrix)
__device__ __forceinline__ void pair_ry(ull& A0, ull& A1,
                                        ull ca2, ull nsa2, ull sa2) {
    ull T0 = fma2(nsa2, A1, mul2(ca2, A0));
    ull T1 = fma2(sa2,  A0, mul2(ca2, A1));
    A0 = T0; A1 = T1;
}
// RY when partner lives in another lane
__device__ __forceinline__ void shfl_ry(ull& A, unsigned mask, ull ca2, ull sp) {
    ull P = __shfl_xor_sync(0xffffffffu, A, mask);
    A = fma2(sp, P, mul2(ca2, A));
}

__global__ __launch_bounds__(THREADS, 1)
void qsim_kernel(const float* __restrict__ state,   // [256,14]
                 const float* __restrict__ vp,      // [3,14,3]
                 const float* __restrict__ hw,      // [14]
                 const float* __restrict__ hb,      // [1]
                 float* __restrict__ out)           // [256]
{
    extern __shared__ float sm[];
    ull*   psi = (ull*)sm;                 // 16384 packed (re,im)
    float* aux = sm + 2 * NSTATE;

    const int tid  = threadIdx.x;
    const int lane = tid & 31;
    const int wa   = tid >> 5;

    // ---- setup stage 1 ----
    if (tid < 42) {
        float a  = 0.5f * vp[tid * 3 + 0];
        float th = 0.5f * vp[tid * 3 + 1];
        float ca, sa, cf, sf;
        sincosf(a,  &sa, &ca);
        sincosf(th, &sf, &cf);
        float* g = aux + OF_GATE + tid * 8;
        g[0] = ca;  g[1] = ca;
        g[2] = -sa; g[3] = -sa;
        g[4] = sa;  g[5] = sa;
        g[6] = cf;  g[7] = sf;
    } else if (tid >= 64 && tid < 78) {
        int w = tid - 64;
        float h = 0.5f * state[blockIdx.x * 14 + w];
        float c, s;
        sincosf(h, &s, &c);
        aux[OF_ENC_C + w] = c;
        aux[OF_ENC_S + w] = s;
    } else if (tid >= 128 && tid < 256) {
        int x = tid - 128;
        float a2 = 0.f;
        #pragma unroll
        for (int p = 0; p < 7; p++)
            a2 += (((x >> p) & 1) ? -1.f : 1.f) * hw[13 - p];
        aux[OF_TLO + x] = a2;
    } else if (tid >= 256 && tid < 384) {
        int x = tid - 256;
        float a2 = 0.f;
        #pragma unroll
        for (int p = 0; p < 7; p++)
            a2 += (((x >> p) & 1) ? -1.f : 1.f) * hw[6 - p];
        aux[OF_THI + x] = a2;
    }
    __syncthreads();

    // ---- setup stage 2 (needs gate table / enc) ----
    if (tid < 16) {
        // rtab: RX factors for idx bits 10..13 (wires 3..0)
        float m = 1.f;
        #pragma unroll
        for (int j = 0; j < 4; j++)
            m *= ((tid >> j) & 1) ? aux[OF_ENC_S + 3 - j] : aux[OF_ENC_C + 3 - j];
        aux[OF_RTAB + tid] = m;
    } else if (tid >= 32 && tid < 96) {
        // phase tables: PA (wires 0-3, idx r=bits13..10) and PB (wires 4-7, r=bits9..6)
        int idx = tid - 32;         // 0..63
        int tb  = idx >> 5;         // 0=PA, 1=PB
        int l   = (idx >> 4) & 1;
        int r   = idx & 15;
        float c = 1.f, s = 0.f;
        #pragma unroll
        for (int j = 0; j < 4; j++) {
            int wire = tb ? (4 + j) : j;
            const float* g = aux + OF_GATE + (l * 14 + wire) * 8;
            float cf = g[6];
            float sf = (((r >> (3 - j)) & 1) ? g[7] : -g[7]);
            float c2 = c * cf - s * sf;
            float s2 = s * cf + c * sf;
            c = c2; s = s2;
        }
        float* p = aux + (tb ? OF_PB : OF_PA) + (l * 16 + r) * 4;
        p[0] = c; p[1] = c; p[2] = -s; p[3] = s;
    }
    // per-thread RX base product over tid bits 0..9 (wires 13..4)
    float P = 1.f;
    #pragma unroll
    for (int j = 0; j < 10; j++)
        P *= ((tid >> j) & 1) ? aux[OF_ENC_S + 13 - j] : aux[OF_ENC_C + 13 - j];
    int pt = __popc(tid);
    __syncthreads();

    // ---- init directly in pass-A register layout: e = tid | (r<<10) ----
    ull A[16];
    #pragma unroll
    for (int r = 0; r < 16; r++) {
        float mag = P * aux[OF_RTAB + r];
        int k = (pt + __popc(r)) & 3;
        float sg = (k == 1 || k == 2) ? -mag : mag;
        float re_ = (k & 1) ? 0.f : sg;
        float im_ = (k & 1) ? sg : 0.f;
        A[r] = pk(re_, im_);
    }

    float acc = 0.f;
    // pass-B layout: idx bit4 <- wa&1 (wire 9), bit5 <- lane bit4 (wire 8)
    const int baseB = (lane & 15) | ((wa & 1) << 4) | (((lane >> 4) & 1) << 5)
                    | ((wa >> 1) << 10);

    #pragma unroll 1
    for (int l = 0; l < 3; l++) {
        // ======== Pass A: e = tid | (r<<10); RY wires 9-13 shfl, 0-3 local ========
        if (l) {
            #pragma unroll
            for (int r = 0; r < 16; r++) {
                int e = tid | (r << 10);
                A[r] = psi[e ^ (e >> 1)];     // gray-folded CNOT perm
            }
            __syncthreads();
        }
        #pragma unroll
        for (int w = 9; w < 14; w++) {
            const ull* g = (const ull*)(aux + OF_GATE + (l * 14 + w) * 8);
            int bit = 13 - w;
            ull ca2 = g[0];
            ull sp  = ((lane >> bit) & 1) ? g[2] : g[1];
            unsigned mask = 1u << bit;
            #pragma unroll
            for (int r = 0; r < 16; r++)
                shfl_ry(A[r], mask, ca2, sp);
        }
        #pragma unroll
        for (int w = 0; w < 4; w++) {
            const ull* g = (const ull*)(aux + OF_GATE + (l * 14 + w) * 8);
            ull ca2 = g[0], nsa2 = g[1], sa2 = g[2];
            int bj = 1 << (3 - w);
            #pragma unroll
            for (int r = 0; r < 16; r++)
                if (!(r & bj))
                    pair_ry(A[r], A[r | bj], ca2, nsa2, sa2);
        }
        if (l < 2) {
            // deferred RZ, pass A: wires 9-13 (per-thread) + wires 0-3 (per-r)
            float tc = 1.f, ts = 0.f;
            #pragma unroll
            for (int w = 9; w < 14; w++) {
                const float* g = aux + OF_GATE + (l * 14 + w) * 8;
                float cf = g[6];
                float sf = (((lane >> (13 - w)) & 1) ? g[7] : -g[7]);
                float c2 = tc * cf - ts * sf;
                float s2 = ts * cf + tc * sf;
                tc = c2; ts = s2;
            }
            ull tpc = pk(tc, tc), tpn = pk(-ts, ts);
            const ull* pa = (const ull*)(aux + OF_PA + l * 64);
            #pragma unroll
            for (int r = 0; r < 16; r++) {
                A[r] = phmul(A[r], tpc, tpn);
                A[r] = phmul(A[r], pa[2 * r], pa[2 * r + 1]);
            }
        }
        #pragma unroll
        for (int r = 0; r < 16; r++)
            psi[tid | (r << 10)] = A[r];
        __syncthreads();

        // ======== Pass B: e = baseB | (r<<6); RY wires 4-7 local, wire 8 shfl ========
        #pragma unroll
        for (int r = 0; r < 16; r++)
            A[r] = psi[baseB | (r << 6)];
        #pragma unroll
        for (int w = 4; w < 8; w++) {
            const ull* g = (const ull*)(aux + OF_GATE + (l * 14 + w) * 8);
            ull ca2 = g[0], nsa2 = g[1], sa2 = g[2];
            int bj = 1 << (7 - w);
            #pragma unroll
            for (int r = 0; r < 16; r++)
                if (!(r & bj))
                    pair_ry(A[r], A[r | bj], ca2, nsa2, sa2);
        }
        {   // wire 8 RY via shfl on lane bit 4 (idx bit 5)
            const ull* g = (const ull*)(aux + OF_GATE + (l * 14 + 8) * 8);
            ull ca2 = g[0];
            ull sp  = ((lane >> 4) & 1) ? g[2] : g[1];
            #pragma unroll
            for (int r = 0; r < 16; r++)
                shfl_ry(A[r], 16u, ca2, sp);
        }

        if (l < 2) {
            // deferred RZ, pass B: wire 8 (per-thread) + wires 4-7 (per-r)
            const float* g8 = aux + OF_GATE + (l * 14 + 8) * 8;
            float cf8 = g8[6];
            float sf8 = (((lane >> 4) & 1) ? g8[7] : -g8[7]);
            ull tpc = pk(cf8, cf8), tpn = pk(-sf8, sf8);
            const ull* pb = (const ull*)(aux + OF_PB + l * 64);
            #pragma unroll
            for (int r = 0; r < 16; r++) {
                A[r] = phmul(A[r], tpc, tpn);
                A[r] = phmul(A[r], pb[2 * r], pb[2 * r + 1]);
            }
            #pragma unroll
            for (int r = 0; r < 16; r++)
                psi[baseB | (r << 6)] = A[r];
            __syncthreads();
        } else {
            // fold final CNOT perm + <Z> + linear head: stored e -> grayDecode(e)
            #pragma unroll
            for (int r = 0; r < 16; r++) {
                int e = baseB | (r << 6);
                int gg = e;
                gg ^= gg >> 1; gg ^= gg >> 2; gg ^= gg >> 4; gg ^= gg >> 8;
                float wt = aux[OF_TLO + (gg & 127)] + aux[OF_THI + ((gg >> 7) & 127)];
                float x, y; upk(A[r], x, y);
                acc = fmaf(fmaf(x, x, y * y), wt, acc);
            }
        }
    }

    // ---- block reduction ----
    #pragma unroll
    for (int o = 16; o; o >>= 1)
        acc += __shfl_xor_sync(0xffffffffu, acc, o);
    if (lane == 0)
        aux[OF_WARP + wa] = acc;
    __syncthreads();
    if (tid < 32) {
        float v = aux[OF_WARP + tid];
        #pragma unroll
        for (int o = 16; o; o >>= 1)
            v += __shfl_xor_sync(0xffffffffu, v, o);
        if (tid == 0)
            out[blockIdx.x] = v + hb[0];
    }
}

extern "C" void kernel_launch(void* const* d_in, const int* in_sizes, int n_in,
                              void* d_out, int out_size)
{
    const float* state = (const float*)d_in[0];
    const float* vp    = (const float*)d_in[1];
    const float* hw    = (const float*)d_in[2];
    const float* hb    = (const float*)d_in[3];
    float* out = (float*)d_out;

    cudaFuncSetAttribute(qsim_kernel,
                         cudaFuncAttributeMaxDynamicSharedMemorySize,
                         (int)SMEM_BYTES);
    qsim_kernel<<<256, THREADS, SMEM_BYTES>>>(state, vp, hw, hb, out);
}

// round 8
// speedup vs baseline: 1.6905x; 1.1045x over previous
#include <cuda_runtime.h>
#include <math.h>

typedef unsigned long long ull;

#define THREADS 1024
#define NSTATE  16384

// aux float offsets (aux = sm + 2*NSTATE floats)
#define OF_GATE 0      // 42 gates * 8 floats: [ca,ca,-sa,-sa,sa,sa,cf,sf]
#define OF_PHI  336    // 42 (phi = 0.5*theta for RZ)
#define OF_ENC_C 384   // 14
#define OF_ENC_S 400   // 14
#define OF_RTAB 416    // 16
#define OF_PB   432    // 2 layers * 16 * 4 floats (phase table, wires 4-7 by r)
#define OF_TL   560    // 2 layers * 32 * 2 floats (wires 8,10-13 by lane)
#define OF_TH   688    // 2 layers * 32 * 2 floats (wires 0-3,9 by warp)
#define OF_TLO  816    // 128
#define OF_THI  944    // 128
#define OF_WARP 1072   // 32
#define AUXF    1104
#define SMEM_BYTES ((2 * NSTATE + AUXF) * sizeof(float))

__device__ __forceinline__ ull pk(float lo, float hi) {
    ull r; asm("mov.b64 %0, {%1,%2};" : "=l"(r) : "f"(lo), "f"(hi)); return r;
}
__device__ __forceinline__ void upk(ull v, float& lo, float& hi) {
    asm("mov.b64 {%0,%1}, %2;" : "=f"(lo), "=f"(hi) : "l"(v));
}
__device__ __forceinline__ ull swap2(ull v) {
    float lo, hi;
    asm("mov.b64 {%0,%1}, %2;" : "=f"(lo), "=f"(hi) : "l"(v));
    ull r; asm("mov.b64 %0, {%1,%2};" : "=l"(r) : "f"(hi), "f"(lo)); return r;
}
__device__ __forceinline__ ull mul2(ull a, ull b) {
    ull d; asm("mul.rn.f32x2 %0, %1, %2;" : "=l"(d) : "l"(a), "l"(b)); return d;
}
__device__ __forceinline__ ull fma2(ull a, ull b, ull c) {
    ull d; asm("fma.rn.f32x2 %0, %1, %2, %3;" : "=l"(d) : "l"(a), "l"(b), "l"(c)); return d;
}
// A * e^{i a}: cr2 = (cos a, cos a), cn2 = (-sin a, sin a)
__device__ __forceinline__ ull phmul(ull A, ull cr2, ull cn2) {
    return fma2(cn2, swap2(A), mul2(cr2, A));
}
__device__ __forceinline__ void pair_ry(ull& A0, ull& A1,
                                        ull ca2, ull nsa2, ull sa2) {
    ull T0 = fma2(nsa2, A1, mul2(ca2, A0));
    ull T1 = fma2(sa2,  A0, mul2(ca2, A1));
    A0 = T0; A1 = T1;
}
__device__ __forceinline__ void shfl_ry(ull& A, unsigned mask, ull ca2, ull sp) {
    ull P = __shfl_xor_sync(0xffffffffu, A, mask);
    A = fma2(sp, P, mul2(ca2, A));
}

__global__ __launch_bounds__(THREADS, 1)
void qsim_kernel(const float* __restrict__ state,   // [256,14]
                 const float* __restrict__ vp,      // [3,14,3]
                 const float* __restrict__ hw,      // [14]
                 const float* __restrict__ hb,      // [1]
                 float* __restrict__ out)           // [256]
{
    extern __shared__ float sm[];
    ull*   psi = (ull*)sm;                 // 16384 packed (re,im)
    float* aux = sm + 2 * NSTATE;

    const int tid  = threadIdx.x;
    const int lane = tid & 31;
    const int wa   = tid >> 5;

    // ---- setup stage 1 ----
    if (tid < 42) {
        float a  = 0.5f * vp[tid * 3 + 0];
        float th = 0.5f * vp[tid * 3 + 1];
        float ca, sa, cf, sf;
        sincosf(a,  &sa, &ca);
        sincosf(th, &sf, &cf);
        float* g = aux + OF_GATE + tid * 8;
        g[0] = ca;  g[1] = ca;
        g[2] = -sa; g[3] = -sa;
        g[4] = sa;  g[5] = sa;
        g[6] = cf;  g[7] = sf;
        aux[OF_PHI + tid] = th;
    } else if (tid >= 64 && tid < 78) {
        int w = tid - 64;
        float h = 0.5f * state[blockIdx.x * 14 + w];
        float c, s;
        sincosf(h, &s, &c);
        aux[OF_ENC_C + w] = c;
        aux[OF_ENC_S + w] = s;
    } else if (tid >= 128 && tid < 256) {
        int x = tid - 128;
        float a2 = 0.f;
        #pragma unroll
        for (int p = 0; p < 7; p++)
            a2 += (((x >> p) & 1) ? -1.f : 1.f) * hw[13 - p];
        aux[OF_TLO + x] = a2;
    } else if (tid >= 256 && tid < 384) {
        int x = tid - 256;
        float a2 = 0.f;
        #pragma unroll
        for (int p = 0; p < 7; p++)
            a2 += (((x >> p) & 1) ? -1.f : 1.f) * hw[6 - p];
        aux[OF_THI + x] = a2;
    }
    __syncthreads();

    // ---- setup stage 2 ----
    if (tid < 16) {
        // rtab: RX factors for idx bits 10..13 (wires 3..0)
        float m = 1.f;
        #pragma unroll
        for (int j = 0; j < 4; j++)
            m *= ((tid >> j) & 1) ? aux[OF_ENC_S + 3 - j] : aux[OF_ENC_C + 3 - j];
        aux[OF_RTAB + tid] = m;
    } else if (tid >= 32 && tid < 64) {
        // PB: wires 4-7 phase, keyed by r = e bits 9..6 (r bit 3-j -> wire 4+j)
        int idx = tid - 32;
        int l = idx >> 4, r = idx & 15;
        const float* ph = aux + OF_PHI + l * 14;
        float ang = 0.f;
        #pragma unroll
        for (int j = 0; j < 4; j++)
            ang += (((r >> (3 - j)) & 1) ? 1.f : -1.f) * ph[4 + j];
        float c, s;
        sincosf(ang, &s, &c);
        float* p = aux + OF_PB + (l * 16 + r) * 4;
        p[0] = c; p[1] = c; p[2] = -s; p[3] = s;
    } else if (tid >= 64 && tid < 128) {
        // TL: wires 8 (lane4), 10-13 (lane3..0), pass-B layout
        int idx = tid - 64;
        int l = idx >> 5, ln = idx & 31;
        const float* ph = aux + OF_PHI + l * 14;
        float ang = (((ln >> 4) & 1) ? ph[8]  : -ph[8])
                  + (((ln >> 3) & 1) ? ph[10] : -ph[10])
                  + (((ln >> 2) & 1) ? ph[11] : -ph[11])
                  + (((ln >> 1) & 1) ? ph[12] : -ph[12])
                  + (( ln       & 1) ? ph[13] : -ph[13]);
        float c, s;
        sincosf(ang, &s, &c);
        aux[OF_TL + (l * 32 + ln) * 2]     = c;
        aux[OF_TL + (l * 32 + ln) * 2 + 1] = s;
    } else if (tid >= 128 && tid < 192) {
        // TH: wires 0-3 (wa bits 4..1), 9 (wa bit 0), pass-B layout
        int idx = tid - 128;
        int l = idx >> 5, w5 = idx & 31;
        const float* ph = aux + OF_PHI + l * 14;
        float ang = (((w5 >> 4) & 1) ? ph[0] : -ph[0])
                  + (((w5 >> 3) & 1) ? ph[1] : -ph[1])
                  + (((w5 >> 2) & 1) ? ph[2] : -ph[2])
                  + (((w5 >> 1) & 1) ? ph[3] : -ph[3])
                  + (( w5       & 1) ? ph[9] : -ph[9]);
        float c, s;
        sincosf(ang, &s, &c);
        aux[OF_TH + (l * 32 + w5) * 2]     = c;
        aux[OF_TH + (l * 32 + w5) * 2 + 1] = s;
    }
    // per-thread RX base product over tid bits 0..9 (wires 13..4)
    float P = 1.f;
    #pragma unroll
    for (int j = 0; j < 10; j++)
        P *= ((tid >> j) & 1) ? aux[OF_ENC_S + 13 - j] : aux[OF_ENC_C + 13 - j];
    int pt = __popc(tid);
    __syncthreads();

    // ---- init directly in pass-A register layout: e = tid | (r<<10) ----
    ull A[16];
    #pragma unroll
    for (int r = 0; r < 16; r++) {
        float mag = P * aux[OF_RTAB + r];
        int k = (pt + __popc(r)) & 3;
        float sg = (k == 1 || k == 2) ? -mag : mag;
        float re_ = (k & 1) ? 0.f : sg;
        float im_ = (k & 1) ? sg : 0.f;
        A[r] = pk(re_, im_);
    }

    float acc = 0.f;
    // pass-B layout: idx bit4 <- wa&1 (wire 9), bit5 <- lane bit4 (wire 8)
    const int baseB = (lane & 15) | ((wa & 1) << 4) | (((lane >> 4) & 1) << 5)
                    | ((wa >> 1) << 10);
    const int g0 = tid ^ (tid >> 1);
    const int g1 = g0 ^ 512;

    #pragma unroll 1
    for (int l = 0; l < 3; l++) {
        // ======== Pass A: e = tid | (r<<10); RY wires 9-13 shfl, 0-3 local ========
        if (l) {
            // gray-folded CNOT perm: src = (r&1 ? g1 : g0) | (gray4(r)<<10)
            #pragma unroll
            for (int r = 0; r < 16; r++) {
                int src = ((r & 1) ? g1 : g0) | (((r ^ (r >> 1)) & 15) << 10);
                A[r] = psi[src];
            }
            __syncthreads();
        }
        #pragma unroll
        for (int w = 9; w < 14; w++) {
            const ull* g = (const ull*)(aux + OF_GATE + (l * 14 + w) * 8);
            int bit = 13 - w;
            ull ca2 = g[0];
            ull sp  = ((lane >> bit) & 1) ? g[2] : g[1];
            unsigned mask = 1u << bit;
            #pragma unroll
            for (int r = 0; r < 16; r++)
                shfl_ry(A[r], mask, ca2, sp);
        }
        #pragma unroll
        for (int w = 0; w < 4; w++) {
            const ull* g = (const ull*)(aux + OF_GATE + (l * 14 + w) * 8);
            ull ca2 = g[0], nsa2 = g[1], sa2 = g[2];
            int bj = 1 << (3 - w);
            #pragma unroll
            for (int r = 0; r < 16; r++)
                if (!(r & bj))
                    pair_ry(A[r], A[r | bj], ca2, nsa2, sa2);
        }
        #pragma unroll
        for (int r = 0; r < 16; r++)
            psi[tid | (r << 10)] = A[r];
        __syncthreads();

        // ======== Pass B: e = baseB | (r<<6); RY wires 4-7 local, wire 8 shfl ========
        #pragma unroll
        for (int r = 0; r < 16; r++)
            A[r] = psi[baseB | (r << 6)];
        #pragma unroll
        for (int w = 4; w < 8; w++) {
            const ull* g = (const ull*)(aux + OF_GATE + (l * 14 + w) * 8);
            ull ca2 = g[0], nsa2 = g[1], sa2 = g[2];
            int bj = 1 << (7 - w);
            #pragma unroll
            for (int r = 0; r < 16; r++)
                if (!(r & bj))
                    pair_ry(A[r], A[r | bj], ca2, nsa2, sa2);
        }
        {   // wire 8 RY via shfl on lane bit 4 (idx bit 5)
            const ull* g = (const ull*)(aux + OF_GATE + (l * 14 + 8) * 8);
            ull ca2 = g[0];
            ull sp  = ((lane >> 4) & 1) ? g[2] : g[1];
            #pragma unroll
            for (int r = 0; r < 16; r++)
                shfl_ry(A[r], 16u, ca2, sp);
        }

        if (l < 2) {
            // ---- ALL 14 wires' RZ phases, applied once: TL[lane]*TH[wa]*PB[r] ----
            const float* tl = aux + OF_TL + (l * 32 + lane) * 2;
            const float* th = aux + OF_TH + (l * 32 + wa) * 2;
            float c1 = tl[0], s1 = tl[1], c2 = th[0], s2 = th[1];
            float C = c1 * c2 - s1 * s2;
            float S = s1 * c2 + c1 * s2;
            ull tpc = pk(C, C), tpn = pk(-S, S);
            const ull* pb = (const ull*)(aux + OF_PB + l * 64);
            #pragma unroll
            for (int r = 0; r < 16; r++) {
                ull t = phmul(A[r], tpc, tpn);
                A[r] = phmul(t, pb[2 * r], pb[2 * r + 1]);
            }
            #pragma unroll
            for (int r = 0; r < 16; r++)
                psi[baseB | (r << 6)] = A[r];
            __syncthreads();
        } else {
            // last layer: phases unobservable; fold CNOT perm + <Z> + head
            #pragma unroll
            for (int r = 0; r < 16; r++) {
                int e = baseB | (r << 6);
                int gg = e;
                gg ^= gg >> 1; gg ^= gg >> 2; gg ^= gg >> 4; gg ^= gg >> 8;
                float wt = aux[OF_TLO + (gg & 127)] + aux[OF_THI + ((gg >> 7) & 127)];
                float x, y; upk(A[r], x, y);
                acc = fmaf(fmaf(x, x, y * y), wt, acc);
            }
        }
    }

    // ---- block reduction ----
    #pragma unroll
    for (int o = 16; o; o >>= 1)
        acc += __shfl_xor_sync(0xffffffffu, acc, o);
    if (lane == 0)
        aux[OF_WARP + wa] = acc;
    __syncthreads();
    if (tid < 32) {
        float v = aux[OF_WARP + tid];
        #pragma unroll
        for (int o = 16; o; o >>= 1)
            v += __shfl_xor_sync(0xffffffffu, v, o);
        if (tid == 0)
            out[blockIdx.x] = v + hb[0];
    }
}

extern "C" void kernel_launch(void* const* d_in, const int* in_sizes, int n_in,
                              void* d_out, int out_size)
{
    const float* state = (const float*)d_in[0];
    const float* vp    = (const float*)d_in[1];
    const float* hw    = (const float*)d_in[2];
    const float* hb    = (const float*)d_in[3];
    float* out = (float*)d_out;

    cudaFuncSetAttribute(qsim_kernel,
                         cudaFuncAttributeMaxDynamicSharedMemorySize,
                         (int)SMEM_BYTES);
    qsim_kernel<<<256, THREADS, SMEM_BYTES>>>(state, vp, hw, hb, out);
}

// round 9
// speedup vs baseline: 1.7630x; 1.0429x over previous
#include <cuda_runtime.h>
#include <math.h>

typedef unsigned long long ull;

#define THREADS 1024
#define NSTATE  16384

// aux float offsets (aux = sm + 2*NSTATE floats)
#define OF_GATE 0      // 42 gates * 8 floats: [ca,ca,-sa,-sa,sa,sa,cf,sf]
#define OF_PHI  336    // 42 (phi = 0.5*theta for RZ), padded
#define OF_ENC_C 384   // 14
#define OF_ENC_S 400   // 14
#define OF_RTAB 416    // 16
#define OF_PR   432    // 2 layers * 16 * 4 (wires 8-11, keyed by pass-C r)
#define OF_TL   560    // 2 layers * 32 * 2 (wires 13,12,7,6,5, keyed by pass-C lane)
#define OF_TH   688    // 2 layers * 32 * 2 (wires 4,3,2,1,0, keyed by pass-C wa)
#define OF_TLO  816    // 128
#define OF_THI  944    // 128
#define OF_WARP 1072   // 32
#define AUXF    1104
#define SMEM_BYTES ((2 * NSTATE + AUXF) * sizeof(float))

__device__ __forceinline__ ull pk(float lo, float hi) {
    ull r; asm("mov.b64 %0, {%1,%2};" : "=l"(r) : "f"(lo), "f"(hi)); return r;
}
__device__ __forceinline__ void upk(ull v, float& lo, float& hi) {
    asm("mov.b64 {%0,%1}, %2;" : "=f"(lo), "=f"(hi) : "l"(v));
}
__device__ __forceinline__ ull swap2(ull v) {
    float lo, hi;
    asm("mov.b64 {%0,%1}, %2;" : "=f"(lo), "=f"(hi) : "l"(v));
    ull r; asm("mov.b64 %0, {%1,%2};" : "=l"(r) : "f"(hi), "f"(lo)); return r;
}
__device__ __forceinline__ ull mul2(ull a, ull b) {
    ull d; asm("mul.rn.f32x2 %0, %1, %2;" : "=l"(d) : "l"(a), "l"(b)); return d;
}
__device__ __forceinline__ ull fma2(ull a, ull b, ull c) {
    ull d; asm("fma.rn.f32x2 %0, %1, %2, %3;" : "=l"(d) : "l"(a), "l"(b), "l"(c)); return d;
}
// A * e^{i a}: cr2 = (c,c), cn2 = (-s,s)
__device__ __forceinline__ ull phmul(ull A, ull cr2, ull cn2) {
    return fma2(cn2, swap2(A), mul2(cr2, A));
}
__device__ __forceinline__ void pair_ry(ull& A0, ull& A1,
                                        ull ca2, ull nsa2, ull sa2) {
    ull T0 = fma2(nsa2, A1, mul2(ca2, A0));
    ull T1 = fma2(sa2,  A0, mul2(ca2, A1));
    A0 = T0; A1 = T1;
}
__device__ __forceinline__ void shfl_ry(ull& A, unsigned mask, ull ca2, ull sp) {
    ull P = __shfl_xor_sync(0xffffffffu, A, mask);
    A = fma2(sp, P, mul2(ca2, A));
}

__global__ __launch_bounds__(THREADS, 1)
void qsim_kernel(const float* __restrict__ state,   // [256,14]
                 const float* __restrict__ vp,      // [3,14,3]
                 const float* __restrict__ hw,      // [14]
                 const float* __restrict__ hb,      // [1]
                 float* __restrict__ out)           // [256]
{
    extern __shared__ float sm[];
    ull*   psi = (ull*)sm;                 // 16384 packed (re,im), address = h(e)
    float* aux = sm + 2 * NSTATE;

    const int tid  = threadIdx.x;
    const int lane = tid & 31;
    const int wa   = tid >> 5;

    // ---- setup stage 1 ----
    if (tid < 42) {
        float a  = 0.5f * vp[tid * 3 + 0];
        float th = 0.5f * vp[tid * 3 + 1];
        float ca, sa, cf, sf;
        sincosf(a,  &sa, &ca);
        sincosf(th, &sf, &cf);
        float* g = aux + OF_GATE + tid * 8;
        g[0] = ca;  g[1] = ca;
        g[2] = -sa; g[3] = -sa;
        g[4] = sa;  g[5] = sa;
        g[6] = cf;  g[7] = sf;
        aux[OF_PHI + tid] = th;
    } else if (tid >= 64 && tid < 78) {
        int w = tid - 64;
        float h = 0.5f * state[blockIdx.x * 14 + w];
        float c, s;
        sincosf(h, &s, &c);
        aux[OF_ENC_C + w] = c;
        aux[OF_ENC_S + w] = s;
    } else if (tid >= 128 && tid < 256) {
        int x = tid - 128;
        float a2 = 0.f;
        #pragma unroll
        for (int p = 0; p < 7; p++)
            a2 += (((x >> p) & 1) ? -1.f : 1.f) * hw[13 - p];
        aux[OF_TLO + x] = a2;
    } else if (tid >= 256 && tid < 384) {
        int x = tid - 256;
        float a2 = 0.f;
        #pragma unroll
        for (int p = 0; p < 7; p++)
            a2 += (((x >> p) & 1) ? -1.f : 1.f) * hw[6 - p];
        aux[OF_THI + x] = a2;
    }
    __syncthreads();

    // ---- setup stage 2 ----
    if (tid < 16) {
        // rtab: RX factors for idx bits 10..13 (wires 3..0)
        float m = 1.f;
        #pragma unroll
        for (int j = 0; j < 4; j++)
            m *= ((tid >> j) & 1) ? aux[OF_ENC_S + 3 - j] : aux[OF_ENC_C + 3 - j];
        aux[OF_RTAB + tid] = m;
    } else if (tid >= 32 && tid < 64) {
        // PR: wires 8-11 phase, keyed by pass-C r (r0->bit2=w11, r1->w10, r2->w9, r3->w8)
        int idx = tid - 32;
        int l = idx >> 4, r = idx & 15;
        const float* ph = aux + OF_PHI + l * 14;
        float ang = (( r       & 1) ? ph[11] : -ph[11])
                  + (((r >> 1) & 1) ? ph[10] : -ph[10])
                  + (((r >> 2) & 1) ? ph[9]  : -ph[9])
                  + (((r >> 3) & 1) ? ph[8]  : -ph[8]);
        float c, s;
        sincosf(ang, &s, &c);
        float* p = aux + OF_PR + (l * 16 + r) * 4;
        p[0] = c; p[1] = c; p[2] = -s; p[3] = s;
    } else if (tid >= 64 && tid < 128) {
        // TL: pass-C lane (ln0->e0=w13, ln1->e1=w12, ln2->e6=w7, ln3->e7=w6, ln4->e8=w5)
        int idx = tid - 64;
        int l = idx >> 5, ln = idx & 31;
        const float* ph = aux + OF_PHI + l * 14;
        float ang = (( ln       & 1) ? ph[13] : -ph[13])
                  + (((ln >> 1) & 1) ? ph[12] : -ph[12])
                  + (((ln >> 2) & 1) ? ph[7]  : -ph[7])
                  + (((ln >> 3) & 1) ? ph[6]  : -ph[6])
                  + (((ln >> 4) & 1) ? ph[5]  : -ph[5]);
        float c, s;
        sincosf(ang, &s, &c);
        aux[OF_TL + (l * 32 + ln) * 2]     = c;
        aux[OF_TL + (l * 32 + ln) * 2 + 1] = s;
    } else if (tid >= 128 && tid < 192) {
        // TH: pass-C wa (w5 bit0->e9=w4, bit1->w3, bit2->w2, bit3->w1, bit4->w0)
        int idx = tid - 128;
        int l = idx >> 5, w5 = idx & 31;
        const float* ph = aux + OF_PHI + l * 14;
        float ang = (( w5       & 1) ? ph[4] : -ph[4])
                  + (((w5 >> 1) & 1) ? ph[3] : -ph[3])
                  + (((w5 >> 2) & 1) ? ph[2] : -ph[2])
                  + (((w5 >> 3) & 1) ? ph[1] : -ph[1])
                  + (((w5 >> 4) & 1) ? ph[0] : -ph[0]);
        float c, s;
        sincosf(ang, &s, &c);
        aux[OF_TH + (l * 32 + w5) * 2]     = c;
        aux[OF_TH + (l * 32 + w5) * 2 + 1] = s;
    }
    // per-thread RX base product over tid bits 0..9 (wires 13..4)
    float P = 1.f;
    #pragma unroll
    for (int j = 0; j < 10; j++)
        P *= ((tid >> j) & 1) ? aux[OF_ENC_S + 13 - j] : aux[OF_ENC_C + 13 - j];
    int pt = __popc(tid);
    __syncthreads();

    // ---- init directly in pass-A register layout: e = tid | (r<<10) ----
    ull A[16];
    #pragma unroll
    for (int r = 0; r < 16; r++) {
        float mag = P * aux[OF_RTAB + r];
        int k = (pt + __popc(r)) & 3;
        float sg = (k == 1 || k == 2) ? -mag : mag;
        float re_ = (k & 1) ? 0.f : sg;
        float im_ = (k & 1) ? sg : 0.f;
        A[r] = pk(re_, im_);
    }

    float acc = 0.f;

    // ---- address bases under global map h(e) = e ^ (((e>>6)&7)<<2) ----
    // Pass A: e = tid | (r<<10)
    const int baseA_st = tid ^ (((tid >> 6) & 7) << 2);
    const int gt = tid ^ (tid >> 1);
    const int baseA_ld = gt ^ (((gt >> 6) & 7) << 2);
    // Pass B: e = lane | ((wa&1)<<5) | (r<<6) | ((wa>>1)<<10)
    const int base_B = lane | ((wa & 1) << 5) | ((wa >> 1) << 10);
    // Pass C: e = (lane&3) | (r<<2) | (((lane>>2)&7)<<6) | (wa<<9)
    const int eC_hi = (((lane >> 2) & 7) << 6) | (wa << 9);
    const int base_C = ((lane & 3) | eC_hi) ^ (((lane >> 2) & 7) << 2);
    const int e_baseC = (lane & 3) | eC_hi;   // logical e base for epilogue

    #pragma unroll 1
    for (int l = 0; l < 3; l++) {
        // ======== Pass A: wires 0-3 pair (r bits 3-0), wires 12,13 shfl ========
        if (l) {
            // gray-folded CNOT perm: addr = baseA_ld ^ (((r ^ (r<<1)) & 31) << 9)
            #pragma unroll
            for (int r = 0; r < 16; r++)
                A[r] = psi[baseA_ld ^ (((r ^ (r << 1)) & 31) << 9)];
            __syncthreads();   // gather set != scatter set
        }
        #pragma unroll
        for (int w = 12; w < 14; w++) {
            const ull* g = (const ull*)(aux + OF_GATE + (l * 14 + w) * 8);
            int bit = 13 - w;
            ull ca2 = g[0];
            ull sp  = ((lane >> bit) & 1) ? g[2] : g[1];
            unsigned mask = 1u << bit;
            #pragma unroll
            for (int r = 0; r < 16; r++)
                shfl_ry(A[r], mask, ca2, sp);
        }
        #pragma unroll
        for (int w = 0; w < 4; w++) {
            const ull* g = (const ull*)(aux + OF_GATE + (l * 14 + w) * 8);
            ull ca2 = g[0], nsa2 = g[1], sa2 = g[2];
            int bj = 1 << (3 - w);
            #pragma unroll
            for (int r = 0; r < 16; r++)
                if (!(r & bj))
                    pair_ry(A[r], A[r | bj], ca2, nsa2, sa2);
        }
        #pragma unroll
        for (int r = 0; r < 16; r++)
            psi[baseA_st | (r << 10)] = A[r];
        __syncthreads();

        // ======== Pass B: wires 4-7 pair (r bits 3-0) ========
        #pragma unroll
        for (int r = 0; r < 16; r++)
            A[r] = psi[base_B ^ ((r << 6) | ((r & 7) << 2))];
        #pragma unroll
        for (int w = 4; w < 8; w++) {
            const ull* g = (const ull*)(aux + OF_GATE + (l * 14 + w) * 8);
            ull ca2 = g[0], nsa2 = g[1], sa2 = g[2];
            int bj = 1 << (7 - w);
            #pragma unroll
            for (int r = 0; r < 16; r++)
                if (!(r & bj))
                    pair_ry(A[r], A[r | bj], ca2, nsa2, sa2);
        }
        #pragma unroll
        for (int r = 0; r < 16; r++)
            psi[base_B ^ ((r << 6) | ((r & 7) << 2))] = A[r];
        __syncthreads();

        // ======== Pass C: wires 8-11 pair (r bits 3-0) ========
        #pragma unroll
        for (int r = 0; r < 16; r++)
            A[r] = psi[base_C ^ (r << 2)];
        #pragma unroll
        for (int w = 8; w < 12; w++) {
            const ull* g = (const ull*)(aux + OF_GATE + (l * 14 + w) * 8);
            ull ca2 = g[0], nsa2 = g[1], sa2 = g[2];
            int bj = 1 << (11 - w);
            #pragma unroll
            for (int r = 0; r < 16; r++)
                if (!(r & bj))
                    pair_ry(A[r], A[r | bj], ca2, nsa2, sa2);
        }

        if (l < 2) {
            // ---- all 14 wires' RZ phases once: TL[lane]*TH[wa]*PR[r] ----
            const float* tl = aux + OF_TL + (l * 32 + lane) * 2;
            const float* th = aux + OF_TH + (l * 32 + wa) * 2;
            float c1 = tl[0], s1 = tl[1], c2 = th[0], s2 = th[1];
            float C = c1 * c2 - s1 * s2;
            float S = s1 * c2 + c1 * s2;
            ull tpc = pk(C, C), tpn = pk(-S, S);
            const ull* pr = (const ull*)(aux + OF_PR + l * 64);
            #pragma unroll
            for (int r = 0; r < 16; r++) {
                ull tv = phmul(A[r], tpc, tpn);
                A[r] = phmul(tv, pr[2 * r], pr[2 * r + 1]);
            }
            #pragma unroll
            for (int r = 0; r < 16; r++)
                psi[base_C ^ (r << 2)] = A[r];
            __syncthreads();
        } else {
            // last layer: phases unobservable; fold CNOT perm + <Z> + head
            #pragma unroll
            for (int r = 0; r < 16; r++) {
                int e = e_baseC | (r << 2);
                int gg = e;
                gg ^= gg >> 1; gg ^= gg >> 2; gg ^= gg >> 4; gg ^= gg >> 8;
                float wt = aux[OF_TLO + (gg & 127)] + aux[OF_THI + ((gg >> 7) & 127)];
                float x, y; upk(A[r], x, y);
                acc = fmaf(fmaf(x, x, y * y), wt, acc);
            }
        }
    }

    // ---- block reduction ----
    #pragma unroll
    for (int o = 16; o; o >>= 1)
        acc += __shfl_xor_sync(0xffffffffu, acc, o);
    if (lane == 0)
        aux[OF_WARP + wa] = acc;
    __syncthreads();
    if (tid < 32) {
        float v = aux[OF_WARP + tid];
        #pragma unroll
        for (int o = 16; o; o >>= 1)
            v += __shfl_xor_sync(0xffffffffu, v, o);
        if (tid == 0)
            out[blockIdx.x] = v + hb[0];
    }
}

extern "C" void kernel_launch(void* const* d_in, const int* in_sizes, int n_in,
                              void* d_out, int out_size)
{
    const float* state = (const float*)d_in[0];
    const float* vp    = (const float*)d_in[1];
    const float* hw    = (const float*)d_in[2];
    const float* hb    = (const float*)d_in[3];
    float* out = (float*)d_out;

    cudaFuncSetAttribute(qsim_kernel,
                         cudaFuncAttributeMaxDynamicSharedMemorySize,
                         (int)SMEM_BYTES);
    qsim_kernel<<<256, THREADS, SMEM_BYTES>>>(state, vp, hw, hb, out);
}